// round 7
// baseline (speedup 1.0000x reference)
#include <cuda_runtime.h>

#define N_NODE 50000
#define N_EDGE 800000
#define D_FEAT 64
#define N_M    11
#define DEPTH  3

#define SCAN_BLK 512
#define N_SBLK ((N_NODE + SCAN_BLK - 1) / SCAN_BLK)   // 98

// ---------------- device scratch (no allocations; zero-init at module load) ----
__device__ float    g_y[2][N_NODE * D_FEAT];   // S x, S^2 x
__device__ float    g_dinv[N_NODE];
__device__ unsigned g_cnt[N_NODE];             // counts; scatter drains back to 0
__device__ unsigned g_rowstart[N_NODE];        // exclusive prefix WITHIN scan block
__device__ unsigned g_bsum[N_SBLK];            // exclusive prefix of block totals
__device__ int2     g_csr[N_EDGE];             // packed {col, val bits}, row-sorted
__device__ float    g_q[16];                   // q[L][k]

// ---------------- per-row edge counts ----------------
__global__ __launch_bounds__(256) void count_kernel(const int* __restrict__ ei) {
    unsigned e = blockIdx.x * blockDim.x + threadIdx.x;
    if (e < N_EDGE) atomicAdd(&g_cnt[ei[e]], 1u);
}

// ---------------- two-level scan, level 1: per-block scan + dinv ----------------
__global__ __launch_bounds__(SCAN_BLK) void block_scan_kernel() {
    __shared__ unsigned warp_sums[SCAN_BLK / 32];
    int t = threadIdx.x;
    int i = blockIdx.x * SCAN_BLK + t;
    unsigned v = (i < N_NODE) ? g_cnt[i] : 0u;
    unsigned s = v;
    #pragma unroll
    for (int o = 1; o < 32; o <<= 1) {
        unsigned n = __shfl_up_sync(0xffffffffu, s, o);
        if ((t & 31) >= o) s += n;
    }
    if ((t & 31) == 31) warp_sums[t >> 5] = s;
    __syncthreads();
    if (t < SCAN_BLK / 32) {
        unsigned ws = warp_sums[t];
        #pragma unroll
        for (int o = 1; o < SCAN_BLK / 32; o <<= 1) {
            unsigned n = __shfl_up_sync(0xffffu, ws, o);
            if (t >= o) ws += n;
        }
        warp_sums[t] = ws;
    }
    __syncthreads();
    unsigned base = (t >= 32) ? warp_sums[(t >> 5) - 1] : 0u;
    unsigned incl = base + s;
    if (i < N_NODE) {
        g_rowstart[i] = incl - v;                    // exclusive within block
        g_dinv[i] = rsqrtf(v ? (float)v : 1.0f);
    }
    if (t == SCAN_BLK - 1) g_bsum[blockIdx.x] = incl;  // block total
}

// ---------------- level 2: exclusive scan of 98 block sums ----------------
__global__ __launch_bounds__(128) void bsum_scan_kernel() {
    __shared__ unsigned s[128];
    int t = threadIdx.x;
    unsigned v = (t < N_SBLK) ? g_bsum[t] : 0u;
    s[t] = v;
    __syncthreads();
    for (int o = 1; o < 128; o <<= 1) {
        unsigned n = (t >= o) ? s[t - o] : 0u;
        __syncthreads();
        s[t] += n;
        __syncthreads();
    }
    if (t < N_SBLK) g_bsum[t] = s[t] - v;   // exclusive block prefix
}

// absolute row start: in-block exclusive + block offset
__device__ __forceinline__ unsigned row_start_abs(unsigned r) {
    return g_rowstart[r] + g_bsum[r >> 9];
}
__device__ __forceinline__ unsigned row_end_abs(unsigned r) {
    return (r == N_NODE - 1) ? (unsigned)N_EDGE : row_start_abs(r + 1);
}

// ---------------- scatter edges into packed CSR ----------------
// val = attr * dinv[col]  (dinv[row] folded into SpMM's per-row output scale).
// atomicSub drains g_cnt back to 0 (pre-launch state restored for replay).
__global__ __launch_bounds__(256) void scatter_kernel(const int* __restrict__ ei,
                                                       const float* __restrict__ attr) {
    unsigned e = blockIdx.x * blockDim.x + threadIdx.x;
    if (e >= N_EDGE) return;
    int r = ei[e];
    int c = ei[e + N_EDGE];
    float v = attr[e] * g_dinv[c];
    unsigned old = atomicSub(&g_cnt[r], 1u);
    unsigned pos = row_start_abs(r) + old - 1u;
    g_csr[pos] = make_int2(c, __float_as_int(v));
}

// ---------------- polynomial coefficient table ----------------
// xs_hist[L][m] = sum_k p[L][m][k] * S^k x  (recurrence linear in S, xs0==x).
// l=-1, r=1 so (l+r)=0, (r-l)=2.
__global__ void coeff_kernel(const float* __restrict__ alphas,
                             const float* __restrict__ w,
                             const float* __restrict__ a_arr,
                             const float* __restrict__ b_arr) {
    if (threadIdx.x != 0 || blockIdx.x != 0) return;
    double q[4][4] = {};
    for (int m = 0; m < N_M; m++) {
        double a = a_arr[m], b = b_arr[m];
        double p[4][4] = {};
        p[0][0] = 1.0;
        double coef1 = (a - b) * 0.5;
        double coef2 = (a + b + 2.0) * 0.5;
        double al0 = alphas[0 * N_M + m];
        p[1][0] = al0 * coef1;
        p[1][1] = al0 * coef2;
        for (int L = 2; L <= DEPTH; L++) {
            double Lf = (double)L;
            double coef_l  = 2.0 * Lf * (Lf + a + b) * (2.0 * Lf - 2.0 + a + b);
            double c_lm1_1 = (2.0 * Lf + a + b - 1.0) * (2.0 * Lf + a + b) * (2.0 * Lf + a + b - 2.0);
            double c_lm1_2 = (2.0 * Lf + a + b - 1.0) * (a * a - b * b);
            double c_lm2   = 2.0 * (Lf - 1.0 + a) * (Lf - 1.0 + b) * (2.0 * Lf + a + b);
            double alL   = alphas[(L - 1) * N_M + m];
            double alLm1 = alphas[(L - 2) * N_M + m];
            double tmp1 = alL * (c_lm1_1 / coef_l);
            double tmp2 = alL * (c_lm1_2 / coef_l);
            double tmp3 = alL * alLm1 * (c_lm2 / coef_l);
            for (int k = 0; k <= L; k++) {
                double t = 0.0;
                if (k > 0) t += tmp1 * p[L - 1][k - 1];
                t -= tmp2 * p[L - 1][k];
                t -= tmp3 * p[L - 2][k];
                p[L][k] = t;
            }
        }
        double wm = w[m];
        for (int L = 0; L < 4; L++)
            for (int k = 0; k < 4; k++)
                q[L][k] += wm * p[L][k];
    }
    for (int i = 0; i < 16; i++) g_q[i] = (float)q[i / 4][i % 4];
}

// ---------------- CSR SpMM: warp per row, float2/lane, 8-wide predicated chunks
// stage 0: x -> g_y[0];  stage 1: g_y[0] -> g_y[1].
// Row result scaled by dinv[row] (folded out of edge values).
__global__ __launch_bounds__(256) void spmm_csr_kernel(const float2* __restrict__ xext,
                                                        int stage) {
    unsigned gid = blockIdx.x * blockDim.x + threadIdx.x;
    unsigned row = gid >> 5;
    if (row >= N_NODE) return;
    unsigned lane = gid & 31u;
    const float2* __restrict__ xin =
        (stage == 0) ? xext : (const float2*)g_y[0];
    float2* yout = (float2*)g_y[stage];

    unsigned s = row_start_abs(row), e = row_end_abs(row);
    float dr = g_dinv[row];

    float2 acc[8];
    #pragma unroll
    for (int k = 0; k < 8; k++) acc[k] = make_float2(0.f, 0.f);

    for (unsigned base = s; base < e; base += 8u) {
        #pragma unroll
        for (int k = 0; k < 8; k++) {
            unsigned i = base + (unsigned)k;
            bool ok = i < e;
            int2 p = ok ? __ldg(g_csr + i) : make_int2(0, 0);
            float2 xv = ok ? __ldg(xin + (unsigned)p.x * 32u + lane)
                           : make_float2(0.f, 0.f);
            float v = __int_as_float(p.y);
            acc[k].x += v * xv.x;
            acc[k].y += v * xv.y;
        }
    }
    float2 r0;
    r0.x = ((acc[0].x + acc[1].x) + (acc[2].x + acc[3].x))
         + ((acc[4].x + acc[5].x) + (acc[6].x + acc[7].x));
    r0.y = ((acc[0].y + acc[1].y) + (acc[2].y + acc[3].y))
         + ((acc[4].y + acc[5].y) + (acc[6].y + acc[7].y));
    r0.x *= dr; r0.y *= dr;
    yout[row * 32u + lane] = r0;
}

// ---------------- final CSR SpMM (S^3 x) fused with output combine ----------
// out[n,L,:] = sum_k q[L][k] * (S^k x)[n,:],  out shape (N_NODE, 4, 64) f32
__global__ __launch_bounds__(256) void spmm_final_kernel(const float2* __restrict__ x,
                                                          float2* __restrict__ out) {
    unsigned gid = blockIdx.x * blockDim.x + threadIdx.x;
    unsigned row = gid >> 5;
    if (row >= N_NODE) return;
    unsigned lane = gid & 31u;
    unsigned s = row_start_abs(row), e = row_end_abs(row);
    float dr = g_dinv[row];
    const float2* __restrict__ y1 = (const float2*)g_y[1];   // S^2 x

    float2 acc[8];
    #pragma unroll
    for (int k = 0; k < 8; k++) acc[k] = make_float2(0.f, 0.f);

    for (unsigned base = s; base < e; base += 8u) {
        #pragma unroll
        for (int k = 0; k < 8; k++) {
            unsigned i = base + (unsigned)k;
            bool ok = i < e;
            int2 p = ok ? __ldg(g_csr + i) : make_int2(0, 0);
            float2 xv = ok ? __ldg(y1 + (unsigned)p.x * 32u + lane)
                           : make_float2(0.f, 0.f);
            float v = __int_as_float(p.y);
            acc[k].x += v * xv.x;
            acc[k].y += v * xv.y;
        }
    }
    float2 s3;
    s3.x = (((acc[0].x + acc[1].x) + (acc[2].x + acc[3].x))
          + ((acc[4].x + acc[5].x) + (acc[6].x + acc[7].x))) * dr;
    s3.y = (((acc[0].y + acc[1].y) + (acc[2].y + acc[3].y))
          + ((acc[4].y + acc[5].y) + (acc[6].y + acc[7].y))) * dr;

    unsigned idx = row * 32u + lane;
    float2 x0 = __ldg(x + idx);
    float2 s1 = ((const float2*)g_y[0])[idx];
    float2 s2 = ((const float2*)g_y[1])[idx];

    float q00 = g_q[0];
    float q10 = g_q[4],  q11 = g_q[5];
    float q20 = g_q[8],  q21 = g_q[9],  q22 = g_q[10];
    float q30 = g_q[12], q31 = g_q[13], q32 = g_q[14], q33 = g_q[15];

    float2 o0, o1, o2, o3;
    o0.x = q00*x0.x;                                      o0.y = q00*x0.y;
    o1.x = q10*x0.x + q11*s1.x;                           o1.y = q10*x0.y + q11*s1.y;
    o2.x = q20*x0.x + q21*s1.x + q22*s2.x;                o2.y = q20*x0.y + q21*s1.y + q22*s2.y;
    o3.x = q30*x0.x + q31*s1.x + q32*s2.x + q33*s3.x;     o3.y = q30*x0.y + q31*s1.y + q32*s2.y + q33*s3.y;

    // out (N_NODE, 4, 64) f32 -> float2 index row*128 + L*32 + lane
    unsigned base = row * 128u + lane;
    out[base +  0u] = o0;
    out[base + 32u] = o1;
    out[base + 64u] = o2;
    out[base + 96u] = o3;
}

// ---------------- launch ----------------
extern "C" void kernel_launch(void* const* d_in, const int* in_sizes, int n_in,
                              void* d_out, int out_size) {
    const float* x      = (const float*)d_in[0];
    const int*   ei     = (const int*)  d_in[1];
    const float* attr   = (const float*)d_in[2];
    const float* alphas = (const float*)d_in[3];
    const float* w      = (const float*)d_in[4];
    const float* a_arr  = (const float*)d_in[5];
    const float* b_arr  = (const float*)d_in[6];
    float* out = (float*)d_out;

    const unsigned rt = (unsigned)N_NODE * 32u;   // warp per row

    count_kernel<<<(N_EDGE + 255) / 256, 256>>>(ei);                 // idx 0
    block_scan_kernel<<<N_SBLK, SCAN_BLK>>>();                       // idx 1
    bsum_scan_kernel<<<1, 128>>>();                                  // idx 2
    scatter_kernel<<<(N_EDGE + 255) / 256, 256>>>(ei, attr);         // idx 3 (profiled)
    coeff_kernel<<<1, 32>>>(alphas, w, a_arr, b_arr);                // idx 4
    spmm_csr_kernel<<<(rt + 255) / 256, 256>>>((const float2*)x, 0); // idx 5
    spmm_csr_kernel<<<(rt + 255) / 256, 256>>>((const float2*)x, 1); // idx 6
    spmm_final_kernel<<<(rt + 255) / 256, 256>>>((const float2*)x, (float2*)out);
}

// round 8
// speedup vs baseline: 1.0518x; 1.0518x over previous
#include <cuda_runtime.h>

#define N_NODE 50000
#define N_EDGE 800000
#define D_FEAT 64
#define N_M    11
#define DEPTH  3

#define SCAN_BLK 512
#define N_SBLK ((N_NODE + SCAN_BLK - 1) / SCAN_BLK)   // 98

// ---------------- device scratch (no allocations; zero-init at module load) ----
__device__ float    g_y[2][N_NODE * D_FEAT];   // S x, S^2 x
__device__ float    g_dinv[N_NODE];
__device__ unsigned g_cnt[N_NODE];             // counts; scatter drains back to 0
__device__ unsigned g_rowstart[N_NODE];        // exclusive prefix WITHIN scan block
__device__ unsigned g_bsum[N_SBLK];            // exclusive prefix of block totals
__device__ int2     g_csr[N_EDGE];             // packed {col, val bits}, row-sorted
__device__ float    g_q[16];                   // q[L][k]

// ---------------- per-row edge counts ----------------
__global__ __launch_bounds__(256) void count_kernel(const int* __restrict__ ei) {
    unsigned e = blockIdx.x * blockDim.x + threadIdx.x;
    if (e < N_EDGE) atomicAdd(&g_cnt[ei[e]], 1u);
}

// ---------------- two-level scan, level 1: per-block scan + dinv ----------------
__global__ __launch_bounds__(SCAN_BLK) void block_scan_kernel() {
    __shared__ unsigned warp_sums[SCAN_BLK / 32];
    int t = threadIdx.x;
    int i = blockIdx.x * SCAN_BLK + t;
    unsigned v = (i < N_NODE) ? g_cnt[i] : 0u;
    unsigned s = v;
    #pragma unroll
    for (int o = 1; o < 32; o <<= 1) {
        unsigned n = __shfl_up_sync(0xffffffffu, s, o);
        if ((t & 31) >= o) s += n;
    }
    if ((t & 31) == 31) warp_sums[t >> 5] = s;
    __syncthreads();
    if (t < SCAN_BLK / 32) {
        unsigned ws = warp_sums[t];
        #pragma unroll
        for (int o = 1; o < SCAN_BLK / 32; o <<= 1) {
            unsigned n = __shfl_up_sync(0xffffu, ws, o);
            if (t >= o) ws += n;
        }
        warp_sums[t] = ws;
    }
    __syncthreads();
    unsigned base = (t >= 32) ? warp_sums[(t >> 5) - 1] : 0u;
    unsigned incl = base + s;
    if (i < N_NODE) {
        g_rowstart[i] = incl - v;                    // exclusive within block
        g_dinv[i] = rsqrtf(v ? (float)v : 1.0f);
    }
    if (t == SCAN_BLK - 1) g_bsum[blockIdx.x] = incl;  // block total
}

// ---------------- level 2: exclusive scan of 98 block sums ----------------
__global__ __launch_bounds__(128) void bsum_scan_kernel() {
    __shared__ unsigned s[128];
    int t = threadIdx.x;
    unsigned v = (t < N_SBLK) ? g_bsum[t] : 0u;
    s[t] = v;
    __syncthreads();
    for (int o = 1; o < 128; o <<= 1) {
        unsigned n = (t >= o) ? s[t - o] : 0u;
        __syncthreads();
        s[t] += n;
        __syncthreads();
    }
    if (t < N_SBLK) g_bsum[t] = s[t] - v;   // exclusive block prefix
}

// absolute row start: in-block exclusive + block offset
__device__ __forceinline__ unsigned row_start_abs(unsigned r) {
    return __ldg(g_rowstart + r) + __ldg(g_bsum + (r >> 9));
}
__device__ __forceinline__ unsigned row_end_abs(unsigned r) {
    return (r == N_NODE - 1) ? (unsigned)N_EDGE : row_start_abs(r + 1);
}

// ---------------- scatter edges into packed CSR ----------------
// val = attr * dinv[col]  (dinv[row] folded into SpMM's per-row output scale).
// atomicSub drains g_cnt back to 0 (pre-launch state restored for replay).
__global__ __launch_bounds__(256) void scatter_kernel(const int* __restrict__ ei,
                                                       const float* __restrict__ attr) {
    unsigned e = blockIdx.x * blockDim.x + threadIdx.x;
    if (e >= N_EDGE) return;
    int r = ei[e];
    int c = ei[e + N_EDGE];
    float v = attr[e] * g_dinv[c];
    unsigned old = atomicSub(&g_cnt[r], 1u);
    unsigned pos = row_start_abs(r) + old - 1u;
    g_csr[pos] = make_int2(c, __float_as_int(v));
}

// ---------------- polynomial coefficient table ----------------
// xs_hist[L][m] = sum_k p[L][m][k] * S^k x  (recurrence linear in S, xs0==x).
// l=-1, r=1 so (l+r)=0, (r-l)=2.
__global__ void coeff_kernel(const float* __restrict__ alphas,
                             const float* __restrict__ w,
                             const float* __restrict__ a_arr,
                             const float* __restrict__ b_arr) {
    if (threadIdx.x != 0 || blockIdx.x != 0) return;
    double q[4][4] = {};
    for (int m = 0; m < N_M; m++) {
        double a = a_arr[m], b = b_arr[m];
        double p[4][4] = {};
        p[0][0] = 1.0;
        double coef1 = (a - b) * 0.5;
        double coef2 = (a + b + 2.0) * 0.5;
        double al0 = alphas[0 * N_M + m];
        p[1][0] = al0 * coef1;
        p[1][1] = al0 * coef2;
        for (int L = 2; L <= DEPTH; L++) {
            double Lf = (double)L;
            double coef_l  = 2.0 * Lf * (Lf + a + b) * (2.0 * Lf - 2.0 + a + b);
            double c_lm1_1 = (2.0 * Lf + a + b - 1.0) * (2.0 * Lf + a + b) * (2.0 * Lf + a + b - 2.0);
            double c_lm1_2 = (2.0 * Lf + a + b - 1.0) * (a * a - b * b);
            double c_lm2   = 2.0 * (Lf - 1.0 + a) * (Lf - 1.0 + b) * (2.0 * Lf + a + b);
            double alL   = alphas[(L - 1) * N_M + m];
            double alLm1 = alphas[(L - 2) * N_M + m];
            double tmp1 = alL * (c_lm1_1 / coef_l);
            double tmp2 = alL * (c_lm1_2 / coef_l);
            double tmp3 = alL * alLm1 * (c_lm2 / coef_l);
            for (int k = 0; k <= L; k++) {
                double t = 0.0;
                if (k > 0) t += tmp1 * p[L - 1][k - 1];
                t -= tmp2 * p[L - 1][k];
                t -= tmp3 * p[L - 2][k];
                p[L][k] = t;
            }
        }
        double wm = w[m];
        for (int L = 0; L < 4; L++)
            for (int k = 0; k < 4; k++)
                q[L][k] += wm * p[L][k];
    }
    for (int i = 0; i < 16; i++) g_q[i] = (float)q[i / 4][i % 4];
}

// ---------------- warp-coalesced row accumulate (shfl broadcast) ----------
// One warp per row. The warp loads up to 32 CSR entries with ONE coalesced
// 256B load, then broadcasts (col,val) lane-by-lane via shfl; every gather
// address is known immediately -> all row gathers issue back-to-back (MLP ~= row len).
__device__ __forceinline__ float2 row_accumulate(const float2* __restrict__ xin,
                                                 unsigned s, unsigned e,
                                                 unsigned lane) {
    float2 acc[4];
    #pragma unroll
    for (int k = 0; k < 4; k++) acc[k] = make_float2(0.f, 0.f);

    for (unsigned chunk = s; chunk < e; chunk += 32u) {
        unsigned idx = chunk + lane;
        int2 p = (idx < e) ? __ldg(g_csr + idx) : make_int2(0, 0);
        unsigned cnt = e - chunk; if (cnt > 32u) cnt = 32u;
        #pragma unroll 4
        for (unsigned k = 0; k < cnt; k++) {
            int   col = __shfl_sync(0xffffffffu, p.x, (int)k);
            int   vb  = __shfl_sync(0xffffffffu, p.y, (int)k);
            float v   = __int_as_float(vb);
            float2 xv = __ldg(xin + (unsigned)col * 32u + lane);
            acc[k & 3u].x += v * xv.x;
            acc[k & 3u].y += v * xv.y;
        }
    }
    float2 r;
    r.x = (acc[0].x + acc[1].x) + (acc[2].x + acc[3].x);
    r.y = (acc[0].y + acc[1].y) + (acc[2].y + acc[3].y);
    return r;
}

// ---------------- CSR SpMM: warp per row, float2 per lane ----------------
// stage 0: x -> g_y[0];  stage 1: g_y[0] -> g_y[1].
// Row result scaled by dinv[row] (folded out of edge values).
__global__ __launch_bounds__(256) void spmm_csr_kernel(const float2* __restrict__ xext,
                                                        int stage) {
    unsigned gid = blockIdx.x * blockDim.x + threadIdx.x;
    unsigned row = gid >> 5;
    if (row >= N_NODE) return;
    unsigned lane = gid & 31u;
    const float2* __restrict__ xin =
        (stage == 0) ? xext : (const float2*)g_y[0];
    float2* yout = (float2*)g_y[stage];

    unsigned s = row_start_abs(row), e = row_end_abs(row);
    float dr = g_dinv[row];
    float2 r = row_accumulate(xin, s, e, lane);
    r.x *= dr; r.y *= dr;
    yout[row * 32u + lane] = r;
}

// ---------------- final CSR SpMM (S^3 x) fused with output combine ----------
// out[n,L,:] = sum_k q[L][k] * (S^k x)[n,:],  out shape (N_NODE, 4, 64) f32
__global__ __launch_bounds__(256) void spmm_final_kernel(const float2* __restrict__ x,
                                                          float2* __restrict__ out) {
    unsigned gid = blockIdx.x * blockDim.x + threadIdx.x;
    unsigned row = gid >> 5;
    if (row >= N_NODE) return;
    unsigned lane = gid & 31u;
    unsigned s = row_start_abs(row), e = row_end_abs(row);
    float dr = g_dinv[row];
    const float2* __restrict__ y1 = (const float2*)g_y[1];   // S^2 x

    float2 s3 = row_accumulate(y1, s, e, lane);
    s3.x *= dr; s3.y *= dr;

    unsigned idx = row * 32u + lane;
    float2 x0 = __ldg(x + idx);
    float2 s1 = ((const float2*)g_y[0])[idx];
    float2 s2 = ((const float2*)g_y[1])[idx];

    float q00 = g_q[0];
    float q10 = g_q[4],  q11 = g_q[5];
    float q20 = g_q[8],  q21 = g_q[9],  q22 = g_q[10];
    float q30 = g_q[12], q31 = g_q[13], q32 = g_q[14], q33 = g_q[15];

    float2 o0, o1, o2, o3;
    o0.x = q00*x0.x;                                      o0.y = q00*x0.y;
    o1.x = q10*x0.x + q11*s1.x;                           o1.y = q10*x0.y + q11*s1.y;
    o2.x = q20*x0.x + q21*s1.x + q22*s2.x;                o2.y = q20*x0.y + q21*s1.y + q22*s2.y;
    o3.x = q30*x0.x + q31*s1.x + q32*s2.x + q33*s3.x;     o3.y = q30*x0.y + q31*s1.y + q32*s2.y + q33*s3.y;

    // out (N_NODE, 4, 64) f32 -> float2 index row*128 + L*32 + lane
    unsigned base = row * 128u + lane;
    out[base +  0u] = o0;
    out[base + 32u] = o1;
    out[base + 64u] = o2;
    out[base + 96u] = o3;
}

// ---------------- launch ----------------
extern "C" void kernel_launch(void* const* d_in, const int* in_sizes, int n_in,
                              void* d_out, int out_size) {
    const float* x      = (const float*)d_in[0];
    const int*   ei     = (const int*)  d_in[1];
    const float* attr   = (const float*)d_in[2];
    const float* alphas = (const float*)d_in[3];
    const float* w      = (const float*)d_in[4];
    const float* a_arr  = (const float*)d_in[5];
    const float* b_arr  = (const float*)d_in[6];
    float* out = (float*)d_out;

    const unsigned rt = (unsigned)N_NODE * 32u;   // warp per row

    count_kernel<<<(N_EDGE + 255) / 256, 256>>>(ei);                 // idx 0
    block_scan_kernel<<<N_SBLK, SCAN_BLK>>>();                       // idx 1
    bsum_scan_kernel<<<1, 128>>>();                                  // idx 2
    scatter_kernel<<<(N_EDGE + 255) / 256, 256>>>(ei, attr);         // idx 3 (profiled)
    coeff_kernel<<<1, 32>>>(alphas, w, a_arr, b_arr);                // idx 4
    spmm_csr_kernel<<<(rt + 255) / 256, 256>>>((const float2*)x, 0); // idx 5
    spmm_csr_kernel<<<(rt + 255) / 256, 256>>>((const float2*)x, 1); // idx 6
    spmm_final_kernel<<<(rt + 255) / 256, 256>>>((const float2*)x, (float2*)out);
}

// round 9
// speedup vs baseline: 1.0891x; 1.0355x over previous
#include <cuda_runtime.h>

#define N_NODE 50000
#define N_EDGE 800000
#define D_FEAT 64
#define N_M    11
#define DEPTH  3

#define SCAN_BLK 512
#define N_SBLK ((N_NODE + SCAN_BLK - 1) / SCAN_BLK)   // 98

// ---------------- device scratch (no allocations; zero-init at module load) ----
__device__ float    g_y[2][N_NODE * D_FEAT];   // S x, S^2 x
__device__ float    g_dinv[N_NODE];
__device__ unsigned g_cnt[N_NODE];             // counts; scatter drains back to 0
__device__ unsigned g_rowstart[N_NODE];        // exclusive prefix WITHIN scan block
__device__ unsigned g_bsum[N_SBLK];            // block totals -> exclusive prefix
__device__ unsigned g_done;                    // scan completion counter (self-reset)
__device__ int2     g_csr[N_EDGE];             // packed {col, val bits}, row-sorted
__device__ float    g_q[16];                   // q[L][k]

// ---------------- per-row edge counts ----------------
__global__ __launch_bounds__(256) void count_kernel(const int* __restrict__ ei) {
    unsigned e = blockIdx.x * blockDim.x + threadIdx.x;
    if (e < N_EDGE) atomicAdd(&g_cnt[ei[e]], 1u);
}

// ---------------- fused two-level scan (single launch) ----------------
// Level 1: per-block exclusive scan of counts + dinv. Level 2: the LAST block
// to finish scans the 98 block totals in-place (threadfence + atomic counter).
__global__ __launch_bounds__(SCAN_BLK) void scan_kernel() {
    __shared__ unsigned warp_sums[SCAN_BLK / 32];
    __shared__ bool s_last;
    __shared__ unsigned s2[128];
    int t = threadIdx.x;
    int i = blockIdx.x * SCAN_BLK + t;
    unsigned v = (i < N_NODE) ? g_cnt[i] : 0u;
    unsigned s = v;
    #pragma unroll
    for (int o = 1; o < 32; o <<= 1) {
        unsigned n = __shfl_up_sync(0xffffffffu, s, o);
        if ((t & 31) >= o) s += n;
    }
    if ((t & 31) == 31) warp_sums[t >> 5] = s;
    __syncthreads();
    if (t < SCAN_BLK / 32) {
        unsigned ws = warp_sums[t];
        #pragma unroll
        for (int o = 1; o < SCAN_BLK / 32; o <<= 1) {
            unsigned n = __shfl_up_sync(0xffffu, ws, o);
            if (t >= o) ws += n;
        }
        warp_sums[t] = ws;
    }
    __syncthreads();
    unsigned base = (t >= 32) ? warp_sums[(t >> 5) - 1] : 0u;
    unsigned incl = base + s;
    if (i < N_NODE) {
        g_rowstart[i] = incl - v;                    // exclusive within block
        g_dinv[i] = rsqrtf(v ? (float)v : 1.0f);
    }
    if (t == SCAN_BLK - 1) g_bsum[blockIdx.x] = incl;  // block total

    // ---- level 2 by the last-finishing block ----
    __threadfence();
    if (t == 0) {
        unsigned old = atomicAdd(&g_done, 1u);
        s_last = (old == (unsigned)(N_SBLK - 1));
    }
    __syncthreads();
    if (s_last) {
        if (t < 128) {
            unsigned bv = (t < N_SBLK) ? g_bsum[t] : 0u;
            s2[t] = bv;
            __syncwarp();
            __syncthreads();
            for (int o = 1; o < 128; o <<= 1) {
                unsigned n = (t >= o) ? s2[t - o] : 0u;
                __syncthreads();
                s2[t] += n;
                __syncthreads();
            }
            if (t < N_SBLK) g_bsum[t] = s2[t] - bv;   // exclusive block prefix
        } else {
            // threads >=128 must participate in the same __syncthreads sequence
            __syncthreads();
            for (int o = 1; o < 128; o <<= 1) { __syncthreads(); __syncthreads(); }
        }
        __syncthreads();
        if (t == 0) g_done = 0u;   // reset for next graph replay
    }
}

// absolute row start: in-block exclusive + block offset
__device__ __forceinline__ unsigned row_start_abs(unsigned r) {
    return __ldg(g_rowstart + r) + __ldg(g_bsum + (r >> 9));
}
__device__ __forceinline__ unsigned row_end_abs(unsigned r) {
    return (r == N_NODE - 1) ? (unsigned)N_EDGE : row_start_abs(r + 1);
}

// ---------------- scatter edges into packed CSR ----------------
// val = attr * dinv[col]  (dinv[row] folded into SpMM's per-row output scale).
// atomicSub drains g_cnt back to 0 (pre-launch state restored for replay).
__global__ __launch_bounds__(256) void scatter_kernel(const int* __restrict__ ei,
                                                       const float* __restrict__ attr) {
    unsigned e = blockIdx.x * blockDim.x + threadIdx.x;
    if (e >= N_EDGE) return;
    int r = ei[e];
    int c = ei[e + N_EDGE];
    float v = attr[e] * g_dinv[c];
    unsigned old = atomicSub(&g_cnt[r], 1u);
    unsigned pos = row_start_abs(r) + old - 1u;
    g_csr[pos] = make_int2(c, __float_as_int(v));
}

// ---------------- polynomial coefficient table ----------------
// xs_hist[L][m] = sum_k p[L][m][k] * S^k x  (recurrence linear in S, xs0==x).
// l=-1, r=1 so (l+r)=0, (r-l)=2.
__global__ void coeff_kernel(const float* __restrict__ alphas,
                             const float* __restrict__ w,
                             const float* __restrict__ a_arr,
                             const float* __restrict__ b_arr) {
    if (threadIdx.x != 0 || blockIdx.x != 0) return;
    double q[4][4] = {};
    for (int m = 0; m < N_M; m++) {
        double a = a_arr[m], b = b_arr[m];
        double p[4][4] = {};
        p[0][0] = 1.0;
        double coef1 = (a - b) * 0.5;
        double coef2 = (a + b + 2.0) * 0.5;
        double al0 = alphas[0 * N_M + m];
        p[1][0] = al0 * coef1;
        p[1][1] = al0 * coef2;
        for (int L = 2; L <= DEPTH; L++) {
            double Lf = (double)L;
            double coef_l  = 2.0 * Lf * (Lf + a + b) * (2.0 * Lf - 2.0 + a + b);
            double c_lm1_1 = (2.0 * Lf + a + b - 1.0) * (2.0 * Lf + a + b) * (2.0 * Lf + a + b - 2.0);
            double c_lm1_2 = (2.0 * Lf + a + b - 1.0) * (a * a - b * b);
            double c_lm2   = 2.0 * (Lf - 1.0 + a) * (Lf - 1.0 + b) * (2.0 * Lf + a + b);
            double alL   = alphas[(L - 1) * N_M + m];
            double alLm1 = alphas[(L - 2) * N_M + m];
            double tmp1 = alL * (c_lm1_1 / coef_l);
            double tmp2 = alL * (c_lm1_2 / coef_l);
            double tmp3 = alL * alLm1 * (c_lm2 / coef_l);
            for (int k = 0; k <= L; k++) {
                double t = 0.0;
                if (k > 0) t += tmp1 * p[L - 1][k - 1];
                t -= tmp2 * p[L - 1][k];
                t -= tmp3 * p[L - 2][k];
                p[L][k] = t;
            }
        }
        double wm = w[m];
        for (int L = 0; L < 4; L++)
            for (int k = 0; k < 4; k++)
                q[L][k] += wm * p[L][k];
    }
    for (int i = 0; i < 16; i++) g_q[i] = (float)q[i / 4][i % 4];
}

// ---------------- CSR SpMM: warp per row, float2/lane, 4-way unroll (R6 best) --
// stage 0: x -> g_y[0];  stage 1: g_y[0] -> g_y[1].
// Row result scaled by dinv[row] (folded out of edge values).
__global__ __launch_bounds__(256) void spmm_csr_kernel(const float2* __restrict__ xext,
                                                        int stage) {
    unsigned gid = blockIdx.x * blockDim.x + threadIdx.x;
    unsigned row = gid >> 5;
    if (row >= N_NODE) return;
    unsigned lane = gid & 31u;
    const float2* __restrict__ xin =
        (stage == 0) ? xext : (const float2*)g_y[0];
    float2* yout = (float2*)g_y[stage];

    unsigned s = row_start_abs(row), e = row_end_abs(row);
    float dr = g_dinv[row];
    float2 a0 = {0.f,0.f}, a1 = {0.f,0.f}, a2 = {0.f,0.f}, a3 = {0.f,0.f};
    unsigned i = s;
    for (; i + 4 <= e; i += 4) {
        int2 p0 = __ldg(g_csr + i);
        int2 p1 = __ldg(g_csr + i + 1);
        int2 p2 = __ldg(g_csr + i + 2);
        int2 p3 = __ldg(g_csr + i + 3);
        float2 x0 = __ldg(xin + (unsigned)p0.x * 32u + lane);
        float2 x1 = __ldg(xin + (unsigned)p1.x * 32u + lane);
        float2 x2 = __ldg(xin + (unsigned)p2.x * 32u + lane);
        float2 x3 = __ldg(xin + (unsigned)p3.x * 32u + lane);
        float v0 = __int_as_float(p0.y), v1 = __int_as_float(p1.y);
        float v2 = __int_as_float(p2.y), v3 = __int_as_float(p3.y);
        a0.x += v0*x0.x; a0.y += v0*x0.y;
        a1.x += v1*x1.x; a1.y += v1*x1.y;
        a2.x += v2*x2.x; a2.y += v2*x2.y;
        a3.x += v3*x3.x; a3.y += v3*x3.y;
    }
    for (; i < e; i++) {
        int2 p0 = __ldg(g_csr + i);
        float2 x0 = __ldg(xin + (unsigned)p0.x * 32u + lane);
        float v0 = __int_as_float(p0.y);
        a0.x += v0*x0.x; a0.y += v0*x0.y;
    }
    a0.x = (a0.x + a1.x) + (a2.x + a3.x);
    a0.y = (a0.y + a1.y) + (a2.y + a3.y);
    a0.x *= dr; a0.y *= dr;
    yout[row * 32u + lane] = a0;
}

// ---------------- final CSR SpMM (S^3 x) fused with output combine ----------
// out[n,L,:] = sum_k q[L][k] * (S^k x)[n,:],  out shape (N_NODE, 4, 64) f32
__global__ __launch_bounds__(256) void spmm_final_kernel(const float2* __restrict__ x,
                                                          float2* __restrict__ out) {
    unsigned gid = blockIdx.x * blockDim.x + threadIdx.x;
    unsigned row = gid >> 5;
    if (row >= N_NODE) return;
    unsigned lane = gid & 31u;
    unsigned s = row_start_abs(row), e = row_end_abs(row);
    float dr = g_dinv[row];
    const float2* __restrict__ y1 = (const float2*)g_y[1];   // S^2 x
    float2 a0 = {0.f,0.f}, a1 = {0.f,0.f}, a2 = {0.f,0.f}, a3 = {0.f,0.f};
    unsigned i = s;
    for (; i + 4 <= e; i += 4) {
        int2 p0 = __ldg(g_csr + i);
        int2 p1 = __ldg(g_csr + i + 1);
        int2 p2 = __ldg(g_csr + i + 2);
        int2 p3 = __ldg(g_csr + i + 3);
        float2 x0 = __ldg(y1 + (unsigned)p0.x * 32u + lane);
        float2 x1 = __ldg(y1 + (unsigned)p1.x * 32u + lane);
        float2 x2 = __ldg(y1 + (unsigned)p2.x * 32u + lane);
        float2 x3 = __ldg(y1 + (unsigned)p3.x * 32u + lane);
        float v0 = __int_as_float(p0.y), v1 = __int_as_float(p1.y);
        float v2 = __int_as_float(p2.y), v3 = __int_as_float(p3.y);
        a0.x += v0*x0.x; a0.y += v0*x0.y;
        a1.x += v1*x1.x; a1.y += v1*x1.y;
        a2.x += v2*x2.x; a2.y += v2*x2.y;
        a3.x += v3*x3.x; a3.y += v3*x3.y;
    }
    for (; i < e; i++) {
        int2 p0 = __ldg(g_csr + i);
        float2 x0 = __ldg(y1 + (unsigned)p0.x * 32u + lane);
        float v0 = __int_as_float(p0.y);
        a0.x += v0*x0.x; a0.y += v0*x0.y;
    }
    float2 s3;
    s3.x = ((a0.x + a1.x) + (a2.x + a3.x)) * dr;
    s3.y = ((a0.y + a1.y) + (a2.y + a3.y)) * dr;

    unsigned idx = row * 32u + lane;
    float2 x0 = __ldg(x + idx);
    float2 s1 = ((const float2*)g_y[0])[idx];
    float2 s2 = ((const float2*)g_y[1])[idx];

    float q00 = g_q[0];
    float q10 = g_q[4],  q11 = g_q[5];
    float q20 = g_q[8],  q21 = g_q[9],  q22 = g_q[10];
    float q30 = g_q[12], q31 = g_q[13], q32 = g_q[14], q33 = g_q[15];

    float2 o0, o1, o2, o3;
    o0.x = q00*x0.x;                                      o0.y = q00*x0.y;
    o1.x = q10*x0.x + q11*s1.x;                           o1.y = q10*x0.y + q11*s1.y;
    o2.x = q20*x0.x + q21*s1.x + q22*s2.x;                o2.y = q20*x0.y + q21*s1.y + q22*s2.y;
    o3.x = q30*x0.x + q31*s1.x + q32*s2.x + q33*s3.x;     o3.y = q30*x0.y + q31*s1.y + q32*s2.y + q33*s3.y;

    // out (N_NODE, 4, 64) f32 -> float2 index row*128 + L*32 + lane
    unsigned base = row * 128u + lane;
    out[base +  0u] = o0;
    out[base + 32u] = o1;
    out[base + 64u] = o2;
    out[base + 96u] = o3;
}

// ---------------- launch ----------------
extern "C" void kernel_launch(void* const* d_in, const int* in_sizes, int n_in,
                              void* d_out, int out_size) {
    const float* x      = (const float*)d_in[0];
    const int*   ei     = (const int*)  d_in[1];
    const float* attr   = (const float*)d_in[2];
    const float* alphas = (const float*)d_in[3];
    const float* w      = (const float*)d_in[4];
    const float* a_arr  = (const float*)d_in[5];
    const float* b_arr  = (const float*)d_in[6];
    float* out = (float*)d_out;

    const unsigned rt = (unsigned)N_NODE * 32u;   // warp per row

    count_kernel<<<(N_EDGE + 255) / 256, 256>>>(ei);                 // idx 0
    scan_kernel<<<N_SBLK, SCAN_BLK>>>();                             // idx 1
    scatter_kernel<<<(N_EDGE + 255) / 256, 256>>>(ei, attr);         // idx 2
    spmm_csr_kernel<<<(rt + 255) / 256, 256>>>((const float2*)x, 0); // idx 3 (profiled)
    coeff_kernel<<<1, 32>>>(alphas, w, a_arr, b_arr);                // idx 4
    spmm_csr_kernel<<<(rt + 255) / 256, 256>>>((const float2*)x, 1); // idx 5
    spmm_final_kernel<<<(rt + 255) / 256, 256>>>((const float2*)x, (float2*)out);
}